// round 4
// baseline (speedup 1.0000x reference)
#include <cuda_runtime.h>

// RALoss fused: loss = sum_i mean_j 10*exp(-sum_{hw}(amax[i,j,hw]-aorg[i,j,hw]))
// Shapes: (4, 64, 512, 512) fp32 x2 inputs, scalar fp32 output.
// Single kernel: grid-wide reduce + last-block finalize (deterministic fixed-order sums).

#define L_DIM 4
#define B_DIM 64
#define PAIRS (L_DIM * B_DIM)        // 256
#define HW (512 * 512)               // 262144 elems per (i,j) map
#define BLKS_PER_PAIR 64
#define THREADS 256
#define F4_PER_THREAD 4              // 16 floats/thread
#define GRID_TOTAL (PAIRS * BLKS_PER_PAIR)   // 16384 blocks

__device__ float g_partials[GRID_TOTAL];
__device__ unsigned int g_done_count;   // zero-init at load; reset by finalize block

__global__ __launch_bounds__(THREADS, 8)
void raloss_fused_kernel(const float4* __restrict__ amax,
                         const float4* __restrict__ aorg,
                         float* __restrict__ out) {
    const int blk  = blockIdx.x;           // 0..63   (chunk within pair)
    const int pair = blockIdx.y;           // 0..255
    const int tid  = threadIdx.x;
    const int warp = tid >> 5;
    const int lane = tid & 31;

    // ---- Phase 1: per-block partial sum of (amax - aorg) over 4096 elems ----
    const long long base = (long long)pair * (HW / 4)
                         + (long long)blk * (THREADS * F4_PER_THREAD);

    float4 ma[F4_PER_THREAD];
    float4 mo[F4_PER_THREAD];
#pragma unroll
    for (int k = 0; k < F4_PER_THREAD; k++) {
        long long idx = base + tid + k * THREADS;
        ma[k] = amax[idx];
        mo[k] = aorg[idx];
    }

    float s = 0.0f;
#pragma unroll
    for (int k = 0; k < F4_PER_THREAD; k++) {
        s += (ma[k].x - mo[k].x) + (ma[k].y - mo[k].y)
           + (ma[k].z - mo[k].z) + (ma[k].w - mo[k].w);
    }

#pragma unroll
    for (int off = 16; off > 0; off >>= 1)
        s += __shfl_xor_sync(0xFFFFFFFFu, s, off);

    __shared__ float warp_sums[THREADS / 32];
    __shared__ bool  s_is_last;
    if (lane == 0) warp_sums[warp] = s;
    __syncthreads();

    if (warp == 0) {
        float v = (lane < (THREADS / 32)) ? warp_sums[lane] : 0.0f;
#pragma unroll
        for (int off = 4; off > 0; off >>= 1)
            v += __shfl_xor_sync(0xFFFFFFFFu, v, off);
        if (lane == 0) {
            g_partials[pair * BLKS_PER_PAIR + blk] = v;
            __threadfence();  // make partial visible before signaling
            unsigned int old = atomicAdd(&g_done_count, 1u);
            s_is_last = (old == (unsigned int)(GRID_TOTAL - 1));
        }
    }
    __syncthreads();

    // ---- Phase 2: last block finalizes (all 16384 partials are in L2) ----
    if (s_is_last) {
        // Thread t owns pair t: fixed-order sum of its 64 partials -> deterministic.
        float d = 0.0f;
#pragma unroll
        for (int k = 0; k < BLKS_PER_PAIR; k++)
            d += __ldcg(&g_partials[tid * BLKS_PER_PAIR + k]);  // L2-only, never stale L1

        // contribution: 10*exp(-d)/B  (sum_i mean_j == sum over all 256 / 64)
        float v = 10.0f * expf(-d) * (1.0f / (float)B_DIM);

#pragma unroll
        for (int off = 16; off > 0; off >>= 1)
            v += __shfl_xor_sync(0xFFFFFFFFu, v, off);

        if (lane == 0) warp_sums[warp] = v;
        __syncthreads();

        if (warp == 0) {
            float w = (lane < (THREADS / 32)) ? warp_sums[lane] : 0.0f;
#pragma unroll
            for (int off = 4; off > 0; off >>= 1)
                w += __shfl_xor_sync(0xFFFFFFFFu, w, off);
            if (lane == 0) {
                out[0] = w;
                g_done_count = 0;   // reset for next graph replay
            }
        }
    }
}

extern "C" void kernel_launch(void* const* d_in, const int* in_sizes, int n_in,
                              void* d_out, int out_size) {
    const float4* amax = (const float4*)d_in[0];
    const float4* aorg = (const float4*)d_in[1];
    float* out = (float*)d_out;

    dim3 grid(BLKS_PER_PAIR, PAIRS, 1);
    raloss_fused_kernel<<<grid, THREADS>>>(amax, aorg, out);
}

// round 5
// speedup vs baseline: 1.0443x; 1.0443x over previous
#include <cuda_runtime.h>

// RALoss fused: loss = sum_i mean_j 10*exp(-sum_{hw}(amax[i,j,hw]-aorg[i,j,hw]))
// Shapes: (4, 64, 512, 512) fp32 x2 inputs, scalar fp32 output.
// Single kernel, 2048 fat blocks (256KB/input each), last-block finalize.

#define L_DIM 4
#define B_DIM 64
#define PAIRS (L_DIM * B_DIM)        // 256
#define HW (512 * 512)               // 262144 elems per (i,j) map
#define BLKS_PER_PAIR 8
#define THREADS 256
#define ITERS 8                      // loop iterations per block
#define F4_PER_ITER 4                // float4 per thread per input per iter
// per block: 256 thr * 8 iters * 4 f4 * 4 = 32768 floats = HW/8  (exact tiling)
#define GRID_TOTAL (PAIRS * BLKS_PER_PAIR)   // 2048 blocks

__device__ float g_partials[GRID_TOTAL];
__device__ unsigned int g_done_count;   // zero-init at load; reset by finalize block

__global__ __launch_bounds__(THREADS)
void raloss_fused_kernel(const float4* __restrict__ amax,
                         const float4* __restrict__ aorg,
                         float* __restrict__ out) {
    const int blk  = blockIdx.x;           // 0..7    (chunk within pair)
    const int pair = blockIdx.y;           // 0..255
    const int tid  = threadIdx.x;
    const int warp = tid >> 5;
    const int lane = tid & 31;

    // float4-unit base: pair*(HW/4) + blk*(HW/4/8)
    const long long base = (long long)pair * (HW / 4)
                         + (long long)blk * (HW / 4 / BLKS_PER_PAIR);

    // 4 independent accumulators to keep FADD chains short.
    float acc0 = 0.0f, acc1 = 0.0f, acc2 = 0.0f, acc3 = 0.0f;

#pragma unroll
    for (int it = 0; it < ITERS; it++) {
        const long long ib = base + (long long)it * (THREADS * F4_PER_ITER) + tid;
        // Front-batch 8 independent 128-bit streaming loads.
        float4 ma0 = __ldcs(&amax[ib + 0 * THREADS]);
        float4 ma1 = __ldcs(&amax[ib + 1 * THREADS]);
        float4 ma2 = __ldcs(&amax[ib + 2 * THREADS]);
        float4 ma3 = __ldcs(&amax[ib + 3 * THREADS]);
        float4 mo0 = __ldcs(&aorg[ib + 0 * THREADS]);
        float4 mo1 = __ldcs(&aorg[ib + 1 * THREADS]);
        float4 mo2 = __ldcs(&aorg[ib + 2 * THREADS]);
        float4 mo3 = __ldcs(&aorg[ib + 3 * THREADS]);

        acc0 += (ma0.x - mo0.x) + (ma0.y - mo0.y) + (ma0.z - mo0.z) + (ma0.w - mo0.w);
        acc1 += (ma1.x - mo1.x) + (ma1.y - mo1.y) + (ma1.z - mo1.z) + (ma1.w - mo1.w);
        acc2 += (ma2.x - mo2.x) + (ma2.y - mo2.y) + (ma2.z - mo2.z) + (ma2.w - mo2.w);
        acc3 += (ma3.x - mo3.x) + (ma3.y - mo3.y) + (ma3.z - mo3.z) + (ma3.w - mo3.w);
    }

    float s = (acc0 + acc1) + (acc2 + acc3);

#pragma unroll
    for (int off = 16; off > 0; off >>= 1)
        s += __shfl_xor_sync(0xFFFFFFFFu, s, off);

    __shared__ float warp_sums[THREADS / 32];
    __shared__ bool  s_is_last;
    if (lane == 0) warp_sums[warp] = s;
    __syncthreads();

    if (warp == 0) {
        float v = (lane < (THREADS / 32)) ? warp_sums[lane] : 0.0f;
#pragma unroll
        for (int off = 4; off > 0; off >>= 1)
            v += __shfl_xor_sync(0xFFFFFFFFu, v, off);
        if (lane == 0) {
            g_partials[pair * BLKS_PER_PAIR + blk] = v;
            __threadfence();  // publish partial before signaling
            unsigned int old = atomicAdd(&g_done_count, 1u);
            s_is_last = (old == (unsigned int)(GRID_TOTAL - 1));
        }
    }
    __syncthreads();

    // ---- Last block finalizes: 2048 partials, all L2-resident ----
    if (s_is_last) {
        // Thread t owns pair t: fixed-order sum of its 8 partials -> deterministic.
        float d = 0.0f;
#pragma unroll
        for (int k = 0; k < BLKS_PER_PAIR; k++)
            d += __ldcg(&g_partials[tid * BLKS_PER_PAIR + k]);  // L2-only view

        // contribution: 10*exp(-d)/B  (sum_i mean_j == sum over all 256 / 64)
        float v = 10.0f * expf(-d) * (1.0f / (float)B_DIM);

#pragma unroll
        for (int off = 16; off > 0; off >>= 1)
            v += __shfl_xor_sync(0xFFFFFFFFu, v, off);

        if (lane == 0) warp_sums[warp] = v;
        __syncthreads();

        if (warp == 0) {
            float w = (lane < (THREADS / 32)) ? warp_sums[lane] : 0.0f;
#pragma unroll
            for (int off = 4; off > 0; off >>= 1)
                w += __shfl_xor_sync(0xFFFFFFFFu, w, off);
            if (lane == 0) {
                out[0] = w;
                g_done_count = 0;   // reset for next graph replay
            }
        }
    }
}

extern "C" void kernel_launch(void* const* d_in, const int* in_sizes, int n_in,
                              void* d_out, int out_size) {
    const float4* amax = (const float4*)d_in[0];
    const float4* aorg = (const float4*)d_in[1];
    float* out = (float*)d_out;

    dim3 grid(BLKS_PER_PAIR, PAIRS, 1);
    raloss_fused_kernel<<<grid, THREADS>>>(amax, aorg, out);
}

// round 6
// speedup vs baseline: 1.0758x; 1.0302x over previous
#include <cuda_runtime.h>

// RALoss fused: loss = sum_i mean_j 10*exp(-sum_{hw}(amax[i,j,hw]-aorg[i,j,hw]))
// Shapes: (4, 64, 512, 512) fp32 x2, scalar fp32 out.
// Single-wave design: 1024 blocks (148 SMs x 8 resident = 1184 capacity),
// regs forced <=32 via launch_bounds, last-block finalize.

#define L_DIM 4
#define B_DIM 64
#define PAIRS (L_DIM * B_DIM)        // 256
#define HW (512 * 512)               // 262144 elems per (i,j) map
#define BLKS_PER_PAIR 4
#define THREADS 256
#define ITERS 32                     // loop iterations per block
#define F4_PER_ITER 2                // float4 per thread per input per iter
// per block: 256 * 32 * 2 * 4 = 65536 floats = HW/4  (exact tiling)
#define GRID_TOTAL (PAIRS * BLKS_PER_PAIR)   // 1024 blocks -> single wave

__device__ float g_partials[GRID_TOTAL];
__device__ unsigned int g_done_count;   // zero-init; reset by finalize block each replay

__global__ __launch_bounds__(THREADS, 8)
void raloss_fused_kernel(const float4* __restrict__ amax,
                         const float4* __restrict__ aorg,
                         float* __restrict__ out) {
    const int blk  = blockIdx.x;           // 0..3    (chunk within pair)
    const int pair = blockIdx.y;           // 0..255
    const int tid  = threadIdx.x;
    const int warp = tid >> 5;
    const int lane = tid & 31;

    // float4-unit base: pair*(HW/4) + blk*(HW/4/4)
    const long long base = (long long)pair * (HW / 4)
                         + (long long)blk * (HW / 4 / BLKS_PER_PAIR);

    float acc0 = 0.0f, acc1 = 0.0f;

#pragma unroll 4
    for (int it = 0; it < ITERS; it++) {
        const long long ib = base + (long long)it * (THREADS * F4_PER_ITER) + tid;
        // 4 independent 128-bit streaming loads in flight per iter.
        float4 ma0 = __ldcs(&amax[ib + 0 * THREADS]);
        float4 ma1 = __ldcs(&amax[ib + 1 * THREADS]);
        float4 mo0 = __ldcs(&aorg[ib + 0 * THREADS]);
        float4 mo1 = __ldcs(&aorg[ib + 1 * THREADS]);

        acc0 += (ma0.x - mo0.x) + (ma0.y - mo0.y) + (ma0.z - mo0.z) + (ma0.w - mo0.w);
        acc1 += (ma1.x - mo1.x) + (ma1.y - mo1.y) + (ma1.z - mo1.z) + (ma1.w - mo1.w);
    }

    float s = acc0 + acc1;

#pragma unroll
    for (int off = 16; off > 0; off >>= 1)
        s += __shfl_xor_sync(0xFFFFFFFFu, s, off);

    __shared__ float warp_sums[THREADS / 32];
    __shared__ bool  s_is_last;
    if (lane == 0) warp_sums[warp] = s;
    __syncthreads();

    if (warp == 0) {
        float v = (lane < (THREADS / 32)) ? warp_sums[lane] : 0.0f;
#pragma unroll
        for (int off = 4; off > 0; off >>= 1)
            v += __shfl_xor_sync(0xFFFFFFFFu, v, off);
        if (lane == 0) {
            g_partials[pair * BLKS_PER_PAIR + blk] = v;
            __threadfence();  // publish partial before signaling
            unsigned int old = atomicAdd(&g_done_count, 1u);
            s_is_last = (old == (unsigned int)(GRID_TOTAL - 1));
        }
    }
    __syncthreads();

    // ---- Last block finalizes: 1024 partials, all L2-resident ----
    if (s_is_last) {
        // Thread t owns pair t: fixed-order sum of its 4 partials -> deterministic.
        float d = 0.0f;
#pragma unroll
        for (int k = 0; k < BLKS_PER_PAIR; k++)
            d += __ldcg(&g_partials[tid * BLKS_PER_PAIR + k]);  // L2-only view

        // contribution: 10*exp(-d)/B  (sum_i mean_j == sum over all 256 / 64)
        float v = 10.0f * expf(-d) * (1.0f / (float)B_DIM);

#pragma unroll
        for (int off = 16; off > 0; off >>= 1)
            v += __shfl_xor_sync(0xFFFFFFFFu, v, off);

        if (lane == 0) warp_sums[warp] = v;
        __syncthreads();

        if (warp == 0) {
            float w = (lane < (THREADS / 32)) ? warp_sums[lane] : 0.0f;
#pragma unroll
            for (int off = 4; off > 0; off >>= 1)
                w += __shfl_xor_sync(0xFFFFFFFFu, w, off);
            if (lane == 0) {
                out[0] = w;
                g_done_count = 0;   // reset for next graph replay
            }
        }
    }
}

extern "C" void kernel_launch(void* const* d_in, const int* in_sizes, int n_in,
                              void* d_out, int out_size) {
    const float4* amax = (const float4*)d_in[0];
    const float4* aorg = (const float4*)d_in[1];
    float* out = (float*)d_out;

    dim3 grid(BLKS_PER_PAIR, PAIRS, 1);
    raloss_fused_kernel<<<grid, THREADS>>>(amax, aorg, out);
}